// round 2
// baseline (speedup 1.0000x reference)
#include <cuda_runtime.h>
#include <cstdint>

#define EPS     1e-8f
#define PSD_EPS 1e-5f

constexpr int B = 8, C = 8, F = 257, T = 1500;
constexpr int BF  = B * F;                       // 2056
constexpr long long FT  = (long long)F * T;      // 385500
constexpr long long BFT = (long long)B * F * T;  // 3084000

// Scratch (no allocations allowed)
__device__ float g_recip[2][B][T];     // 1/(max_f |mask| + eps) per (mask, b, t)
__device__ float g_acc[BF][2][66];     // per (b,f), per mask: [0..7] diag, [8+2p],[9+2p] offdiag re/im, [64] den
__device__ float g_w[BF][C][2];        // conj(weight) per (b,f,c): (re, im)

// ---------------------------------------------------------------------------
// Kernel 1: per-(b,t) max over F of |mask|, store reciprocal of (max+eps)
// ---------------------------------------------------------------------------
__global__ void mask_max_kernel(const float* __restrict__ sm,
                                const float* __restrict__ nm) {
    int nchunk = (T + 255) / 256;           // 6
    int bx = blockIdx.x;                    // 0 .. 2*B*nchunk-1
    int tchunk = bx % nchunk;
    int b = (bx / nchunk) % B;
    int m = bx / (nchunk * B);
    int t = tchunk * 256 + threadIdx.x;
    if (t >= T) return;
    const float* src = (m ? nm : sm) + (long long)b * FT;
    float mx = 0.0f;
    #pragma unroll 4
    for (int f = 0; f < F; f++)
        mx = fmaxf(mx, fabsf(src[(long long)f * T + t]));
    g_recip[m][b][t] = 1.0f / (mx + EPS);
}

// ---------------------------------------------------------------------------
// Kernel 2: per-(b,f) mask-weighted Hermitian outer-product accumulation.
// One block per (b,f), 128 threads stride over t. 130 accumulators/thread,
// tree reduction (deterministic) into g_acc.
// ---------------------------------------------------------------------------
__global__ __launch_bounds__(128) void psd_accum_kernel(
    const float* __restrict__ sm, const float* __restrict__ nm,
    const float* __restrict__ cr, const float* __restrict__ ci) {
    int bf = blockIdx.x;
    int b = bf / F, f = bf % F;
    const float* crb = cr + (long long)b * C * FT + (long long)f * T;
    const float* cib = ci + (long long)b * C * FT + (long long)f * T;
    const float* smb = sm + (long long)b * FT + (long long)f * T;
    const float* nmb = nm + (long long)b * FT + (long long)f * T;
    const float* rs = g_recip[0][b];
    const float* rn = g_recip[1][b];

    // layout: [0..7]=diag_s, [8+2p/9+2p]=offdiag_s, [64]=den_s, +65 for noise
    float acc[130];
    #pragma unroll
    for (int k = 0; k < 130; k++) acc[k] = 0.0f;

    for (int t = threadIdx.x; t < T; t += 128) {
        float xr[8], xi[8];
        #pragma unroll
        for (int c = 0; c < 8; c++) {
            xr[c] = crb[c * FT + t];
            xi[c] = cib[c * FT + t];
        }
        float ms = smb[t] * rs[t];
        float mn = nmb[t] * rn[t];
        acc[64]  += ms;
        acc[129] += mn;
        #pragma unroll
        for (int c = 0; c < 8; c++) {
            float p = xr[c] * xr[c] + xi[c] * xi[c];
            acc[c]      = fmaf(ms, p, acc[c]);
            acc[65 + c] = fmaf(mn, p, acc[65 + c]);
        }
        int p = 0;
        #pragma unroll
        for (int c = 0; c < 8; c++) {
            #pragma unroll
            for (int d = c + 1; d < 8; d++) {
                // o = x_c * conj(x_d)
                float orr = xr[c] * xr[d] + xi[c] * xi[d];
                float oii = xi[c] * xr[d] - xr[c] * xi[d];
                acc[8 + 2 * p]  = fmaf(ms, orr, acc[8 + 2 * p]);
                acc[9 + 2 * p]  = fmaf(ms, oii, acc[9 + 2 * p]);
                acc[73 + 2 * p] = fmaf(mn, orr, acc[73 + 2 * p]);
                acc[74 + 2 * p] = fmaf(mn, oii, acc[74 + 2 * p]);
                p++;
            }
        }
    }

    // deterministic reduction: warp shfl, then cross-warp via shared
    __shared__ float sh[4][130];
    int lane = threadIdx.x & 31, wid = threadIdx.x >> 5;
    #pragma unroll
    for (int k = 0; k < 130; k++) {
        float v = acc[k];
        v += __shfl_down_sync(0xffffffffu, v, 16);
        v += __shfl_down_sync(0xffffffffu, v, 8);
        v += __shfl_down_sync(0xffffffffu, v, 4);
        v += __shfl_down_sync(0xffffffffu, v, 2);
        v += __shfl_down_sync(0xffffffffu, v, 1);
        if (lane == 0) sh[wid][k] = v;
    }
    __syncthreads();
    for (int k = threadIdx.x; k < 130; k += 128) {
        float v = sh[0][k] + sh[1][k] + sh[2][k] + sh[3][k];
        if (k < 65) g_acc[bf][0][k] = v;
        else        g_acc[bf][1][k - 65] = v;
    }
}

// ---------------------------------------------------------------------------
// Kernel 3: per-(b,f) solve. One thread per (b,f): build noise PSD, in-place
// Gauss-Jordan 8x8 complex inverse (no pivoting: matrix is strongly
// diagonally dominant), then tr(ninv@S) and (ninv@S)[:,0] with S fetched
// on the fly; store conj(weight).
// ---------------------------------------------------------------------------
__device__ __forceinline__ int pidx(int c, int d) {
    return c * 7 - (c * (c - 1)) / 2 + (d - c - 1);
}

__device__ __forceinline__ void getS(const float* a, float invs,
                                     int r, int c, float& re, float& im) {
    const float IM0 = PSD_EPS + EPS;
    if (r == c)      { re = a[r] * invs;                 im = IM0; }
    else if (r < c)  { int p = pidx(r, c);
                       re = a[8 + 2 * p] * invs;         im = a[9 + 2 * p] * invs + IM0; }
    else             { int p = pidx(c, r);
                       re = a[8 + 2 * p] * invs;         im = -a[9 + 2 * p] * invs + IM0; }
}

__global__ void solve_kernel() {
    int bf = blockIdx.x * blockDim.x + threadIdx.x;
    if (bf >= BF) return;
    const float IM0 = PSD_EPS + EPS;

    const float* an = g_acc[bf][1];
    float invd = 1.0f / fmaxf(an[64], PSD_EPS);
    float Nr[8][8], Ni[8][8];
    #pragma unroll
    for (int c = 0; c < 8; c++) {
        Nr[c][c] = an[c] * invd + EPS;   // + eye*eps
        Ni[c][c] = IM0;
        #pragma unroll
        for (int d = c + 1; d < 8; d++) {
            int p = pidx(c, d);
            float re = an[8 + 2 * p] * invd, im = an[9 + 2 * p] * invd;
            Nr[c][d] = re; Ni[c][d] = im + IM0;
            Nr[d][c] = re; Ni[d][c] = -im + IM0;
        }
    }

    // in-place Gauss-Jordan inverse (complex, no pivoting)
    #pragma unroll
    for (int k = 0; k < 8; k++) {
        float pr = Nr[k][k], pi = Ni[k][k];
        float s = 1.0f / (pr * pr + pi * pi);
        float qr = pr * s, qi = -pi * s;
        #pragma unroll
        for (int j = 0; j < 8; j++) if (j != k) {
            float ar = Nr[k][j], ai = Ni[k][j];
            Nr[k][j] = ar * qr - ai * qi;
            Ni[k][j] = ar * qi + ai * qr;
        }
        Nr[k][k] = qr; Ni[k][k] = qi;
        #pragma unroll
        for (int i = 0; i < 8; i++) if (i != k) {
            float fr = Nr[i][k], fi = Ni[i][k];
            #pragma unroll
            for (int j = 0; j < 8; j++) if (j != k) {
                float br = Nr[k][j], bi = Ni[k][j];
                Nr[i][j] -= fr * br - fi * bi;
                Ni[i][j] -= fr * bi + fi * br;
            }
            Nr[i][k] = -(fr * qr - fi * qi);
            Ni[i][k] = -(fr * qi + fi * qr);
        }
    }

    // ninv += 1j*eps
    #pragma unroll
    for (int c = 0; c < 8; c++)
        #pragma unroll
        for (int d = 0; d < 8; d++) Ni[c][d] += EPS;

    const float* as_ = g_acc[bf][0];
    float invs = 1.0f / fmaxf(as_[64], PSD_EPS);

    // tr = sum_{c,d} ninv[c][d] * S[d][c]  (+ eps)
    float trr = EPS, tri = 0.0f;
    #pragma unroll
    for (int c = 0; c < 8; c++) {
        #pragma unroll
        for (int d = 0; d < 8; d++) {
            float sr, si; getS(as_, invs, d, c, sr, si);
            float ar = Nr[c][d], ai = Ni[c][d];
            trr += ar * sr - ai * si;
            tri += ar * si + ai * sr;
        }
    }
    // u[c] = sum_d ninv[c][d] * S[d][0]
    float ur[8], ui[8];
    #pragma unroll
    for (int c = 0; c < 8; c++) {
        float sumr = 0.0f, sumi = 0.0f;
        #pragma unroll
        for (int d = 0; d < 8; d++) {
            float sr, si; getS(as_, invs, d, 0, sr, si);
            float ar = Nr[c][d], ai = Ni[c][d];
            sumr += ar * sr - ai * si;
            sumi += ar * si + ai * sr;
        }
        ur[c] = sumr; ui[c] = sumi;
    }
    float tm = 1.0f / (trr * trr + tri * tri);
    #pragma unroll
    for (int c = 0; c < 8; c++) {
        float wr = (ur[c] * trr + ui[c] * tri) * tm;   // Re(u/tr)
        float wi = (ui[c] * trr - ur[c] * tri) * tm;   // Im(u/tr)
        g_w[bf][c][0] = wr;
        g_w[bf][c][1] = -wi;                           // store conj(weight)
    }
}

// ---------------------------------------------------------------------------
// Kernel 4: beamform. out[b,f,t] = sum_c conj(w) * cm
// ---------------------------------------------------------------------------
__global__ __launch_bounds__(256) void beamform_kernel(
    const float* __restrict__ cr, const float* __restrict__ ci,
    float* __restrict__ out) {
    int bf = blockIdx.x;
    int b = bf / F, f = bf % F;
    float wr[8], wi[8];
    #pragma unroll
    for (int c = 0; c < 8; c++) {
        wr[c] = g_w[bf][c][0];
        wi[c] = g_w[bf][c][1];
    }
    const float* crb = cr + (long long)b * C * FT + (long long)f * T;
    const float* cib = ci + (long long)b * C * FT + (long long)f * T;
    float* outr = out + (long long)bf * T;
    float* outi = out + BFT + (long long)bf * T;
    for (int t = threadIdx.x; t < T; t += 256) {
        float orr = 0.0f, oii = 0.0f;
        #pragma unroll
        for (int c = 0; c < 8; c++) {
            float xr = crb[c * FT + t], xi = cib[c * FT + t];
            orr += wr[c] * xr - wi[c] * xi;
            oii += wr[c] * xi + wi[c] * xr;
        }
        outr[t] = orr;
        outi[t] = oii;
    }
}

// ---------------------------------------------------------------------------
extern "C" void kernel_launch(void* const* d_in, const int* in_sizes, int n_in,
                              void* d_out, int out_size) {
    const float* sm = (const float*)d_in[0];
    const float* nm = (const float*)d_in[1];
    const float* cr = (const float*)d_in[2];
    const float* ci = (const float*)d_in[3];
    float* out = (float*)d_out;

    int nchunk = (T + 255) / 256;
    mask_max_kernel<<<2 * B * nchunk, 256>>>(sm, nm);
    psd_accum_kernel<<<BF, 128>>>(sm, nm, cr, ci);
    solve_kernel<<<(BF + 127) / 128, 128>>>();
    beamform_kernel<<<BF, 256>>>(cr, ci, out);
}